// round 1
// baseline (speedup 1.0000x reference)
#include <cuda_runtime.h>
#include <cstdint>

// ---------------- problem constants ----------------
#define NPTS 20000
#define MNBR 20
#define ERBF 20
#define HDIM 128
#define BCRY 200
#define NBLK 8          // nodes per conv block
#define PI_F 3.14159265358979f

typedef unsigned long long u64;

// ---------------- device scratch (static: no allocs allowed) ----------------
__device__ int   g_order;                       // 1 => d_in[2] is vdw_fea (dict order)
__device__ float g_nodesA[NPTS * HDIM];
__device__ float g_nodesB[NPTS * HDIM];
__device__ float g_rbf_che[NPTS * MNBR * ERBF];
__device__ float g_rbf_vdw[NPTS * MNBR * ERBF];
__device__ float g_ST[(size_t)NPTS * 1024];     // per-node: [S_che 256 | T_che 256 | S_vdw 256 | T_vdw 256], interleaved (filt,core) pairs
__device__ float g_Wcat[128 * 1024];
__device__ float g_We_che[ERBF * 256];
__device__ float g_be_che[256];
__device__ float g_We_vdw[ERBF * 256];
__device__ float g_be_vdw[256];

// ---------------- f32x2 packed math (Blackwell FFMA2) ----------------
__device__ __forceinline__ u64 pk2(float lo, float hi) {
    u64 r; asm("mov.b64 %0, {%1,%2};" : "=l"(r) : "f"(lo), "f"(hi)); return r;
}
__device__ __forceinline__ void upk2(u64 v, float& lo, float& hi) {
    asm("mov.b64 {%0,%1}, %2;" : "=f"(lo), "=f"(hi) : "l"(v));
}
__device__ __forceinline__ u64 fma2(u64 a, u64 b, u64 c) {
    u64 d; asm("fma.rn.f32x2 %0, %1, %2, %3;" : "=l"(d) : "l"(a), "l"(b), "l"(c)); return d;
}
__device__ __forceinline__ u64 add2(u64 a, u64 b) {
    u64 d; asm("add.rn.f32x2 %0, %1, %2;" : "=l"(d) : "l"(a), "l"(b)); return d;
}

// ---------------- activations ----------------
__device__ __forceinline__ float softplusf_(float x) {
    return fmaxf(x, 0.f) + __logf(1.f + __expf(-fabsf(x)));
}
__device__ __forceinline__ float gatef_(float f, float c) {
    float sig = __fdividef(1.f, 1.f + __expf(-f));
    return sig * softplusf_(c);
}

// ---------------- 0: detect input ordering ----------------
__global__ void detect_kernel(const unsigned* __restrict__ p2) {
    if (threadIdx.x == 0) g_order = (p2[0] > 1000000u) ? 1 : 0;
}

// ---------------- 1: node embedding  nodes = AE @ embW + embB ----------------
__global__ __launch_bounds__(128) void embed_kernel(
    const float* __restrict__ ae, const float* __restrict__ W, const float* __restrict__ b)
{
    __shared__ float sW[13 * 128];
    __shared__ float sa[13];
    int h = threadIdx.x;
    for (int i = h; i < 13 * 128; i += 128) sW[i] = W[i];
    float bb = b[h];
    int n0 = blockIdx.x * 32;
    for (int nn = 0; nn < 32; nn++) {
        int n = n0 + nn;
        __syncthreads();
        if (h < 13) sa[h] = ae[n * 13 + h];
        __syncthreads();
        float s = bb;
#pragma unroll
        for (int k = 0; k < 13; k++) s = fmaf(sa[k], sW[k * 128 + h], s);
        g_nodesA[(size_t)n * 128 + h] = s;
    }
}

// ---------------- 2: radial basis (both halves), computed once ----------------
__global__ void rbf_kernel(const float* __restrict__ che,
                           const float* __restrict__ p2, const float* __restrict__ p3)
{
    const float* vdw = g_order ? p2 : p3;
    int i = blockIdx.x * blockDim.x + threadIdx.x;
    if (i >= NPTS * MNBR) return;
    {
        float d = che[i];
        float inv = __fdividef(1.f, d);
        float env = 0.5f * (__cosf(d * (PI_F / 8.f)) + 1.f) * inv;
        bool in = d < 8.f;
#pragma unroll
        for (int k = 0; k < ERBF; k++) {
            float r = in ? __sinf(d * ((k + 1) * (PI_F / 8.f))) * env : 0.f;
            g_rbf_che[(size_t)i * ERBF + k] = r;
        }
    }
    {
        float d = vdw[i];
        float inv = __fdividef(1.f, d);
        float env = 0.5f * (__cosf(d * (PI_F / 12.f)) + 1.f) * inv;
        bool in = d < 12.f;
#pragma unroll
        for (int k = 0; k < ERBF; k++) {
            float r = in ? __sinf(d * ((k + 1) * (PI_F / 12.f))) * env : 0.f;
            g_rbf_vdw[(size_t)i * ERBF + k] = r;
        }
    }
}

// ---------------- 3: per-layer folded edge weights  We = fW @ gW[H:2H], be = fb @ gW[H:2H] + gb ----------------
__global__ __launch_bounds__(256) void we_kernel(
    const float* __restrict__ fW, const float* __restrict__ fb,
    const float* __restrict__ gW, const float* __restrict__ gb, int which)
{
    float* We = which ? g_We_vdw : g_We_che;
    float* be = which ? g_be_vdw : g_be_che;
    int c = threadIdx.x;       // 0..255
    int k = blockIdx.x;        // 0..20 (20 == bias block)
    if (k < ERBF) {
        float s = 0.f;
        for (int hh = 0; hh < 128; hh++) s = fmaf(fW[k * 128 + hh], gW[(128 + hh) * 256 + c], s);
        We[k * 256 + c] = s;
    } else {
        float s = gb[c];
        for (int hh = 0; hh < 128; hh++) s = fmaf(fb[hh], gW[(128 + hh) * 256 + c], s);
        be[c] = s;
    }
}

// ---------------- 4: build concatenated weight for ST GEMM (with (filt,core) interleave) ----------------
__global__ void wcat_kernel(const float* __restrict__ cheG, const float* __restrict__ vdwG)
{
    int idx = blockIdx.x * blockDim.x + threadIdx.x;
    if (idx >= 128 * 1024) return;
    int k = idx >> 10;
    int c = idx & 1023;
    int region = c >> 8;         // 0 S_che, 1 T_che, 2 S_vdw, 3 T_vdw
    int cc = c & 255;
    int h = cc >> 1, p = cc & 1; // p=0 filt, p=1 core
    const float* gW = (region < 2) ? cheG : vdwG;
    int row = ((region & 1) ? 256 : 0) + k;
    g_Wcat[idx] = gW[row * 256 + p * 128 + h];
}

// ---------------- 5: ST GEMM  [N,128] @ [128,1024] (SIMT sgemm, 128x128 tile) ----------------
__global__ __launch_bounds__(256) void gemm_kernel(int src)
{
    const float* __restrict__ A = src ? g_nodesB : g_nodesA;
    const float* __restrict__ Bm = g_Wcat;
    float* __restrict__ C = g_ST;

    __shared__ float As[8][128];
    __shared__ float Bs[8][128];

    int r0 = blockIdx.x * 128;
    int c0 = blockIdx.y * 128;
    int tid = threadIdx.x;
    int tx = tid & 15, ty = tid >> 4;

    float acc[8][8];
#pragma unroll
    for (int i = 0; i < 8; i++)
#pragma unroll
        for (int j = 0; j < 8; j++) acc[i][j] = 0.f;

    int arow = tid >> 1;
    int acol = (tid & 1) * 4;
    int brow = tid >> 5;
    int bcol = (tid & 31) * 4;

    for (int k0 = 0; k0 < 128; k0 += 8) {
        float4 av = make_float4(0.f, 0.f, 0.f, 0.f);
        int gr = r0 + arow;
        if (gr < NPTS) av = *(const float4*)(A + (size_t)gr * 128 + k0 + acol);
        As[acol + 0][arow] = av.x;
        As[acol + 1][arow] = av.y;
        As[acol + 2][arow] = av.z;
        As[acol + 3][arow] = av.w;
        *(float4*)(&Bs[brow][bcol]) = *(const float4*)(Bm + (size_t)(k0 + brow) * 1024 + c0 + bcol);
        __syncthreads();
#pragma unroll
        for (int k = 0; k < 8; k++) {
            float ar[8], br[8];
#pragma unroll
            for (int i = 0; i < 8; i++) ar[i] = As[k][ty * 8 + i];
#pragma unroll
            for (int j = 0; j < 8; j++) br[j] = Bs[k][tx * 8 + j];
#pragma unroll
            for (int i = 0; i < 8; i++)
#pragma unroll
                for (int j = 0; j < 8; j++) acc[i][j] = fmaf(ar[i], br[j], acc[i][j]);
        }
        __syncthreads();
    }
#pragma unroll
    for (int i = 0; i < 8; i++) {
        int gr = r0 + ty * 8 + i;
        if (gr < NPTS) {
            *(float4*)(C + (size_t)gr * 1024 + c0 + tx * 8) =
                make_float4(acc[i][0], acc[i][1], acc[i][2], acc[i][3]);
            *(float4*)(C + (size_t)gr * 1024 + c0 + tx * 8 + 4) =
                make_float4(acc[i][4], acc[i][5], acc[i][6], acc[i][7]);
        }
    }
}

// ---------------- 6: fused gated conv (both halves) + residual softplus ----------------
__global__ __launch_bounds__(128) void conv_kernel(
    const int* __restrict__ p2i, const int* __restrict__ p3i,
    const int* __restrict__ vdw_idx_g, int src)
{
    const int* che_idx = g_order ? p3i : p2i;
    const float* __restrict__ nodes = src ? g_nodesB : g_nodesA;
    float* __restrict__ nodes_out = src ? g_nodesA : g_nodesB;

    __shared__ float2 s_r[MNBR * ERBF];
    __shared__ int s_idx[MNBR];
    __shared__ float s_acc[NBLK * 128];

    int h = threadIdx.x;
    int n0 = blockIdx.x * NBLK;
#pragma unroll
    for (int i = 0; i < NBLK; i++) s_acc[i * 128 + h] = 0.f;

#pragma unroll 1
    for (int half = 0; half < 2; half++) {
        const float* We = half ? g_We_vdw : g_We_che;
        const float* be = half ? g_be_vdw : g_be_che;
        const float* rbf = half ? g_rbf_vdw : g_rbf_che;
        const int* idxp = half ? vdw_idx_g : che_idx;
        int toff = half ? 768 : 256;
        int soff = half ? 512 : 0;

        u64 w[ERBF];
#pragma unroll
        for (int k = 0; k < ERBF; k++) w[k] = pk2(We[k * 256 + h], We[k * 256 + 128 + h]);
        u64 bvec = pk2(be[h], be[128 + h]);

#pragma unroll 1
        for (int nn = 0; nn < NBLK; nn++) {
            int n = n0 + nn;
            __syncthreads();
            for (int i = h; i < MNBR * ERBF; i += 128) {
                float v = rbf[(size_t)n * (MNBR * ERBF) + i];
                s_r[i] = make_float2(v, v);
            }
            if (h < MNBR) s_idx[h] = idxp[n * MNBR + h];
            __syncthreads();

            u64 sv = *(const u64*)(g_ST + (size_t)n * 1024 + soff + 2 * h);
            float a = 0.f;
            int j = s_idx[0];
            u64 t = *(const u64*)(g_ST + (size_t)j * 1024 + toff + 2 * h);
#pragma unroll 1
            for (int m = 0; m < MNBR; m++) {
                u64 tcur = t;
                if (m < MNBR - 1) {
                    int jn = s_idx[m + 1];
                    t = *(const u64*)(g_ST + (size_t)jn * 1024 + toff + 2 * h);
                }
                u64 e0 = bvec, e1 = pk2(0.f, 0.f);
#pragma unroll
                for (int k = 0; k < ERBF; k += 2) {
                    e0 = fma2(*(const u64*)&s_r[m * ERBF + k],     w[k],     e0);
                    e1 = fma2(*(const u64*)&s_r[m * ERBF + k + 1], w[k + 1], e1);
                }
                u64 g = add2(add2(e0, e1), add2(sv, tcur));
                float gf, gc; upk2(g, gf, gc);
                a += gatef_(gf, gc);
            }
            s_acc[nn * 128 + h] += a;
        }
    }
#pragma unroll
    for (int nn = 0; nn < NBLK; nn++) {
        int n = n0 + nn;
        float r = nodes[(size_t)n * 128 + h] + s_acc[nn * 128 + h];
        nodes_out[(size_t)n * 128 + h] = softplusf_(r);
    }
}

// ---------------- 7: pooling + MLP head ----------------
__global__ __launch_bounds__(128) void pool_kernel(
    const int* __restrict__ num_atoms,
    const float* __restrict__ fc1W, const float* __restrict__ fc1b,
    const float* __restrict__ outW, const float* __restrict__ outb,
    float* __restrict__ out, int src)
{
    const float* __restrict__ nodes = src ? g_nodesB : g_nodesA;
    __shared__ float sA[128];
    __shared__ float sB[128];
    __shared__ int s_sc[2];
    int b = blockIdx.x, h = threadIdx.x;
    if (h == 0) {
        int st = 0;
        for (int i = 0; i < b; i++) st += num_atoms[i];
        s_sc[0] = st; s_sc[1] = num_atoms[b];
    }
    __syncthreads();
    int start = s_sc[0], cnt = s_sc[1];
    float s = 0.f;
    for (int a = 0; a < cnt; a++) s += nodes[(size_t)(start + a) * 128 + h];
    sA[h] = softplusf_(s / (float)cnt);
    __syncthreads();
    float t = fc1b[h];
    for (int k = 0; k < 128; k++) t = fmaf(sA[k], fc1W[k * 128 + h], t);
    sB[h] = softplusf_(t) * outW[h];
    __syncthreads();
    for (int off = 64; off > 0; off >>= 1) {
        if (h < off) sB[h] += sB[h + off];
        __syncthreads();
    }
    if (h == 0) out[b] = sB[0] + outb[0];
}

// ---------------- launch ----------------
extern "C" void kernel_launch(void* const* d_in, const int* in_sizes, int n_in,
                              void* d_out, int out_size)
{
    const float* ae      = (const float*)d_in[0];
    const float* che_fea = (const float*)d_in[1];
    const void*  p2      = d_in[2];
    const void*  p3      = d_in[3];
    const int*   vdw_idx = (const int*)d_in[4];
    const int*   natoms  = (const int*)d_in[5];
    const float* embW    = (const float*)d_in[6];
    const float* embB    = (const float*)d_in[7];
    const float* cheFW   = (const float*)d_in[8];
    const float* cheFb   = (const float*)d_in[9];
    const float* cheGW   = (const float*)d_in[10];
    const float* cheGb   = (const float*)d_in[11];
    const float* vdwFW   = (const float*)d_in[12];
    const float* vdwFb   = (const float*)d_in[13];
    const float* vdwGW   = (const float*)d_in[14];
    const float* vdwGb   = (const float*)d_in[15];
    const float* fc1W    = (const float*)d_in[16];
    const float* fc1b    = (const float*)d_in[17];
    const float* outW    = (const float*)d_in[18];
    const float* outb    = (const float*)d_in[19];

    detect_kernel<<<1, 32>>>((const unsigned*)p2);
    embed_kernel<<<NPTS / 32, 128>>>(ae, embW, embB);
    rbf_kernel<<<(NPTS * MNBR + 255) / 256, 256>>>(che_fea, (const float*)p2, (const float*)p3);

    int src = 0;
    for (int i = 0; i < 3; i++) {
        we_kernel<<<21, 256>>>(cheFW + i * 2560, cheFb + i * 128,
                               cheGW + (size_t)i * 98304, cheGb + i * 256, 0);
        we_kernel<<<21, 256>>>(vdwFW + i * 2560, vdwFb + i * 128,
                               vdwGW + (size_t)i * 98304, vdwGb + i * 256, 1);
        wcat_kernel<<<512, 256>>>(cheGW + (size_t)i * 98304, vdwGW + (size_t)i * 98304);
        gemm_kernel<<<dim3((NPTS + 127) / 128, 8), 256>>>(src);
        conv_kernel<<<NPTS / NBLK, 128>>>((const int*)p2, (const int*)p3, vdw_idx, src);
        src ^= 1;
    }
    pool_kernel<<<BCRY, 128>>>(natoms, fc1W, fc1b, outW, outb, (float*)d_out, src);
}

// round 2
// speedup vs baseline: 1.1794x; 1.1794x over previous
#include <cuda_runtime.h>
#include <cstdint>

// ---------------- problem constants ----------------
#define NPTS 20000
#define MNBR 20
#define ERBF 20
#define HDIM 128
#define BCRY 200
#define NBLK 8
#define PI_F 3.14159265358979f

typedef unsigned long long u64;

// ---------------- device scratch ----------------
__device__ int   g_order;
__device__ float g_nodesA[NPTS * HDIM];
__device__ float g_nodesB[NPTS * HDIM];
__device__ float g_ST[(size_t)NPTS * 1024];   // [S_che|T_che|S_vdw|T_vdw] interleaved (filt,core)
__device__ float g_Wcat[3 * 131072];
__device__ float g_We[3 * 2 * ERBF * 256];
__device__ float g_be[3 * 2 * 256];

// ---------------- f32x2 packed math ----------------
__device__ __forceinline__ u64 pk2(float lo, float hi) {
    u64 r; asm("mov.b64 %0, {%1,%2};" : "=l"(r) : "f"(lo), "f"(hi)); return r;
}
__device__ __forceinline__ void upk2(u64 v, float& lo, float& hi) {
    asm("mov.b64 {%0,%1}, %2;" : "=f"(lo), "=f"(hi) : "l"(v));
}
__device__ __forceinline__ u64 fma2(u64 a, u64 b, u64 c) {
    u64 d; asm("fma.rn.f32x2 %0, %1, %2, %3;" : "=l"(d) : "l"(a), "l"(b), "l"(c)); return d;
}
__device__ __forceinline__ u64 add2(u64 a, u64 b) {
    u64 d; asm("add.rn.f32x2 %0, %1, %2;" : "=l"(d) : "l"(a), "l"(b)); return d;
}

// ---------------- activations ----------------
__device__ __forceinline__ float softplusf_(float x) {
    return fmaxf(x, 0.f) + __logf(1.f + __expf(-fabsf(x)));
}
__device__ __forceinline__ float gatef_(float f, float c) {
    float sig = __fdividef(1.f, 1.f + __expf(-f));
    return sig * softplusf_(c);
}

// ---------------- 0: detect input ordering ----------------
__global__ void detect_kernel(const unsigned* __restrict__ p2) {
    if (threadIdx.x == 0) g_order = (p2[0] > 1000000u) ? 1 : 0;
}

// ---------------- 1: node embedding (16 nodes / block) ----------------
__global__ __launch_bounds__(128) void embed_kernel(
    const float* __restrict__ ae, const float* __restrict__ W, const float* __restrict__ b)
{
    __shared__ float sW[13 * 128];
    __shared__ float sa[16 * 13];
    int h = threadIdx.x;
    for (int i = h; i < 13 * 128; i += 128) sW[i] = W[i];
    int n0 = blockIdx.x * 16;
    for (int i = h; i < 16 * 13; i += 128) sa[i] = ae[n0 * 13 + i];
    float bb = b[h];
    __syncthreads();
#pragma unroll
    for (int nn = 0; nn < 16; nn++) {
        float s = bb;
#pragma unroll
        for (int k = 0; k < 13; k++) s = fmaf(sa[nn * 13 + k], sW[k * 128 + h], s);
        g_nodesA[(size_t)(n0 + nn) * 128 + h] = s;
    }
}

// ---------------- 2: folded edge weights for all layers/halves ----------------
__global__ __launch_bounds__(256) void we_kernel(
    const float* __restrict__ cheFW, const float* __restrict__ cheFb,
    const float* __restrict__ cheGW, const float* __restrict__ cheGb,
    const float* __restrict__ vdwFW, const float* __restrict__ vdwFb,
    const float* __restrict__ vdwGW, const float* __restrict__ vdwGb)
{
    int half = blockIdx.y, layer = blockIdx.z;
    const float* fW = (half ? vdwFW : cheFW) + layer * 2560;
    const float* fb = (half ? vdwFb : cheFb) + layer * 128;
    const float* gW = (half ? vdwGW : cheGW) + (size_t)layer * 98304;
    const float* gb = (half ? vdwGb : cheGb) + layer * 256;
    float* We = g_We + (layer * 2 + half) * 5120;
    float* be = g_be + (layer * 2 + half) * 256;
    int c = threadIdx.x;
    int k = blockIdx.x;
    if (k < ERBF) {
        float s = 0.f;
        for (int hh = 0; hh < 128; hh++) s = fmaf(fW[k * 128 + hh], gW[(size_t)(128 + hh) * 256 + c], s);
        We[k * 256 + c] = s;
    } else {
        float s = gb[c];
        for (int hh = 0; hh < 128; hh++) s = fmaf(fb[hh], gW[(size_t)(128 + hh) * 256 + c], s);
        be[c] = s;
    }
}

// ---------------- 3: concatenated GEMM weights, all layers ----------------
__global__ void wcat_kernel(const float* __restrict__ cheG, const float* __restrict__ vdwG)
{
    int layer = blockIdx.y;
    int idx = blockIdx.x * blockDim.x + threadIdx.x;
    if (idx >= 128 * 1024) return;
    int k = idx >> 10;
    int c = idx & 1023;
    int region = c >> 8;         // 0 S_che, 1 T_che, 2 S_vdw, 3 T_vdw
    int cc = c & 255;
    int h = cc >> 1, p = cc & 1; // p=0 filt, p=1 core
    const float* gW = ((region < 2) ? cheG : vdwG) + (size_t)layer * 98304;
    int row = ((region & 1) ? 256 : 0) + k;
    g_Wcat[(size_t)layer * 131072 + idx] = gW[(size_t)row * 256 + p * 128 + h];
}

// ---------------- 4: ST GEMM  [N,128]x[128,1024], f32x2, double-buffered ----------------
__global__ __launch_bounds__(256, 2) void gemm_kernel(int src, int layer)
{
    const float* __restrict__ A = src ? g_nodesB : g_nodesA;
    const float* __restrict__ Bm = g_Wcat + (size_t)layer * 131072;
    float* __restrict__ C = g_ST;

    __shared__ float As[2][8][128];
    __shared__ float Bs[2][8][128];

    int r0 = blockIdx.x * 128;
    int c0 = blockIdx.y * 128;
    int tid = threadIdx.x;
    int tx = tid & 15, ty = tid >> 4;

    u64 acc[8][4];
#pragma unroll
    for (int i = 0; i < 8; i++)
#pragma unroll
        for (int j = 0; j < 4; j++) acc[i][j] = pk2(0.f, 0.f);

    int arow = tid >> 1;
    int acol = (tid & 1) * 4;
    int brow = tid >> 5;
    int bcol = (tid & 31) * 4;
    int gr = r0 + arow;
    const float* Aptr = A + (size_t)gr * 128 + acol;
    const float* Bptr = Bm + (size_t)brow * 1024 + c0 + bcol;

    float4 av = make_float4(0.f, 0.f, 0.f, 0.f);
    if (gr < NPTS) av = *(const float4*)Aptr;
    float4 bv = *(const float4*)Bptr;
    As[0][acol + 0][arow] = av.x;
    As[0][acol + 1][arow] = av.y;
    As[0][acol + 2][arow] = av.z;
    As[0][acol + 3][arow] = av.w;
    *(float4*)&Bs[0][brow][bcol] = bv;
    __syncthreads();

#pragma unroll 1
    for (int t = 0; t < 16; t++) {
        int cur = t & 1;
        float4 avn = make_float4(0.f, 0.f, 0.f, 0.f), bvn;
        if (t < 15) {
            if (gr < NPTS) avn = *(const float4*)(Aptr + 8 * (t + 1));
            bvn = *(const float4*)(Bptr + (size_t)8 * (t + 1) * 1024);
        }
#pragma unroll
        for (int k = 0; k < 8; k++) {
            u64 b2[4];
#pragma unroll
            for (int j = 0; j < 4; j++) b2[j] = *(const u64*)&Bs[cur][k][tx * 8 + 2 * j];
#pragma unroll
            for (int i = 0; i < 8; i++) {
                float a_ = As[cur][k][ty * 8 + i];
                u64 a2 = pk2(a_, a_);
#pragma unroll
                for (int j = 0; j < 4; j++) acc[i][j] = fma2(a2, b2[j], acc[i][j]);
            }
        }
        if (t < 15) {
            As[cur ^ 1][acol + 0][arow] = avn.x;
            As[cur ^ 1][acol + 1][arow] = avn.y;
            As[cur ^ 1][acol + 2][arow] = avn.z;
            As[cur ^ 1][acol + 3][arow] = avn.w;
            *(float4*)&Bs[cur ^ 1][brow][bcol] = bvn;
        }
        __syncthreads();
    }

#pragma unroll
    for (int i = 0; i < 8; i++) {
        int gr2 = r0 + ty * 8 + i;
        if (gr2 < NPTS) {
            float4 lo, hi;
            upk2(acc[i][0], lo.x, lo.y);
            upk2(acc[i][1], lo.z, lo.w);
            upk2(acc[i][2], hi.x, hi.y);
            upk2(acc[i][3], hi.z, hi.w);
            *(float4*)(C + (size_t)gr2 * 1024 + c0 + tx * 8) = lo;
            *(float4*)(C + (size_t)gr2 * 1024 + c0 + tx * 8 + 4) = hi;
        }
    }
}

// ---------------- 5: fused gated conv (both halves) + on-the-fly RBF ----------------
__global__ __launch_bounds__(128) void conv_kernel(
    const float* __restrict__ che_fea, const float* __restrict__ p2f, const float* __restrict__ p3f,
    const int* __restrict__ p2i, const int* __restrict__ p3i,
    const int* __restrict__ vdw_idx, int src, int layer)
{
    const int* che_idx = g_order ? p3i : p2i;
    const float* vdw_fea = g_order ? p2f : p3f;
    const float* __restrict__ nodes = src ? g_nodesB : g_nodesA;
    float* __restrict__ nodes_out = src ? g_nodesA : g_nodesB;

    __shared__ __align__(16) u64 s_r[MNBR * ERBF];
    __shared__ float s_env[MNBR];
    __shared__ float s_d[MNBR];
    __shared__ int s_idx[MNBR];
    __shared__ float s_acc[NBLK * 128];

    int h = threadIdx.x;
    int n0 = blockIdx.x * NBLK;
#pragma unroll
    for (int i = 0; i < NBLK; i++) s_acc[i * 128 + h] = 0.f;

#pragma unroll 1
    for (int half = 0; half < 2; half++) {
        const float* We = g_We + (layer * 2 + half) * 5120;
        const float* be = g_be + (layer * 2 + half) * 256;
        const float* feap = half ? vdw_fea : che_fea;
        const int* idxp = half ? vdw_idx : che_idx;
        float invc = half ? (PI_F / 12.f) : (PI_F / 8.f);
        float cut = half ? 12.f : 8.f;
        int toff = half ? 768 : 256;
        int soff = half ? 512 : 0;

        u64 w[ERBF];
#pragma unroll
        for (int k = 0; k < ERBF; k++) w[k] = pk2(We[k * 256 + h], We[k * 256 + 128 + h]);
        u64 bvec = pk2(be[h], be[128 + h]);

#pragma unroll 1
        for (int nn = 0; nn < NBLK; nn++) {
            int n = n0 + nn;
            __syncthreads();
            if (h < MNBR) {
                float d = feap[n * MNBR + h];
                s_idx[h] = idxp[n * MNBR + h];
                s_d[h] = d;
                float env = 0.5f * (__cosf(d * invc) + 1.f);
                s_env[h] = (d < cut) ? env * __fdividef(1.f, d) : 0.f;
            }
            __syncthreads();
            for (int i = h; i < MNBR * ERBF; i += 128) {
                int m = i / ERBF;
                int k = i - m * ERBF;
                float v = __sinf(s_d[m] * ((float)(k + 1) * invc)) * s_env[m];
                s_r[i] = pk2(v, v);
            }
            __syncthreads();

            u64 sv = *(const u64*)(g_ST + (size_t)n * 1024 + soff + 2 * h);
            float a = 0.f;
            int j0 = s_idx[0];
            u64 t = *(const u64*)(g_ST + (size_t)j0 * 1024 + toff + 2 * h);
#pragma unroll 1
            for (int m = 0; m < MNBR; m++) {
                u64 tcur = t;
                if (m < MNBR - 1) {
                    int jn = s_idx[m + 1];
                    t = *(const u64*)(g_ST + (size_t)jn * 1024 + toff + 2 * h);
                }
                u64 e0 = bvec, e1 = pk2(0.f, 0.f);
#pragma unroll
                for (int k = 0; k < ERBF; k += 2) {
                    ulonglong2 rr = *(const ulonglong2*)&s_r[m * ERBF + k];
                    e0 = fma2(rr.x, w[k], e0);
                    e1 = fma2(rr.y, w[k + 1], e1);
                }
                u64 g = add2(add2(e0, e1), add2(sv, tcur));
                float gf, gc; upk2(g, gf, gc);
                a += gatef_(gf, gc);
            }
            s_acc[nn * 128 + h] += a;
        }
    }
#pragma unroll
    for (int nn = 0; nn < NBLK; nn++) {
        int n = n0 + nn;
        float r = nodes[(size_t)n * 128 + h] + s_acc[nn * 128 + h];
        nodes_out[(size_t)n * 128 + h] = softplusf_(r);
    }
}

// ---------------- 6: pooling + MLP head (parallel prefix) ----------------
__global__ __launch_bounds__(128) void pool_kernel(
    const int* __restrict__ num_atoms,
    const float* __restrict__ fc1W, const float* __restrict__ fc1b,
    const float* __restrict__ outW, const float* __restrict__ outb,
    float* __restrict__ out, int src)
{
    const float* __restrict__ nodes = src ? g_nodesB : g_nodesA;
    __shared__ float sA[128];
    __shared__ float sB[128];
    __shared__ int sred[128];
    int b = blockIdx.x, h = threadIdx.x;

    int v = 0;
    for (int i = h; i < b; i += 128) v += num_atoms[i];
    sred[h] = v;
    __syncthreads();
    for (int off = 64; off > 0; off >>= 1) {
        if (h < off) sred[h] += sred[h + off];
        __syncthreads();
    }
    int start = sred[0];
    int cnt = num_atoms[b];

    float s = 0.f;
    for (int a = 0; a < cnt; a++) s += nodes[(size_t)(start + a) * 128 + h];
    sA[h] = softplusf_(s / (float)cnt);
    __syncthreads();
    float t = fc1b[h];
    for (int k = 0; k < 128; k++) t = fmaf(sA[k], fc1W[k * 128 + h], t);
    sB[h] = softplusf_(t) * outW[h];
    __syncthreads();
    for (int off = 64; off > 0; off >>= 1) {
        if (h < off) sB[h] += sB[h + off];
        __syncthreads();
    }
    if (h == 0) out[b] = sB[0] + outb[0];
}

// ---------------- launch ----------------
extern "C" void kernel_launch(void* const* d_in, const int* in_sizes, int n_in,
                              void* d_out, int out_size)
{
    const float* ae      = (const float*)d_in[0];
    const float* che_fea = (const float*)d_in[1];
    const void*  p2      = d_in[2];
    const void*  p3      = d_in[3];
    const int*   vdw_idx = (const int*)d_in[4];
    const int*   natoms  = (const int*)d_in[5];
    const float* embW    = (const float*)d_in[6];
    const float* embB    = (const float*)d_in[7];
    const float* cheFW   = (const float*)d_in[8];
    const float* cheFb   = (const float*)d_in[9];
    const float* cheGW   = (const float*)d_in[10];
    const float* cheGb   = (const float*)d_in[11];
    const float* vdwFW   = (const float*)d_in[12];
    const float* vdwFb   = (const float*)d_in[13];
    const float* vdwGW   = (const float*)d_in[14];
    const float* vdwGb   = (const float*)d_in[15];
    const float* fc1W    = (const float*)d_in[16];
    const float* fc1b    = (const float*)d_in[17];
    const float* outW    = (const float*)d_in[18];
    const float* outb    = (const float*)d_in[19];

    detect_kernel<<<1, 32>>>((const unsigned*)p2);
    embed_kernel<<<NPTS / 16, 128>>>(ae, embW, embB);
    we_kernel<<<dim3(21, 2, 3), 256>>>(cheFW, cheFb, cheGW, cheGb, vdwFW, vdwFb, vdwGW, vdwGb);
    wcat_kernel<<<dim3(512, 3), 256>>>(cheGW, vdwGW);

    int src = 0;
    for (int i = 0; i < 3; i++) {
        gemm_kernel<<<dim3((NPTS + 127) / 128, 8), 256>>>(src, i);
        conv_kernel<<<NPTS / NBLK, 128>>>(che_fea, (const float*)p2, (const float*)p3,
                                          (const int*)p2, (const int*)p3, vdw_idx, src, i);
        src ^= 1;
    }
    pool_kernel<<<BCRY, 128>>>(natoms, fc1W, fc1b, outW, outb, (float*)d_out, src);
}

// round 3
// speedup vs baseline: 1.2138x; 1.0292x over previous
#include <cuda_runtime.h>
#include <cstdint>

// ---------------- problem constants ----------------
#define NPTS 20000
#define MNBR 20
#define ERBF 20
#define HDIM 128
#define BCRY 200
#define NBLK 8
#define PI_F 3.14159265358979f

typedef unsigned long long u64;

// ---------------- device scratch ----------------
__device__ int   g_order;
__device__ float g_nodesA[NPTS * HDIM];
__device__ float g_nodesB[NPTS * HDIM];
__device__ float g_ST[(size_t)NPTS * 1024];   // [S_che|T_che|S_vdw|T_vdw] interleaved (filt,core)
__device__ float g_Wcat[3 * 131072];
__device__ float g_We[3 * 2 * ERBF * 256];
__device__ float g_be[3 * 2 * 256];

// ---------------- f32x2 packed math ----------------
__device__ __forceinline__ u64 pk2(float lo, float hi) {
    u64 r; asm("mov.b64 %0, {%1,%2};" : "=l"(r) : "f"(lo), "f"(hi)); return r;
}
__device__ __forceinline__ void upk2(u64 v, float& lo, float& hi) {
    asm("mov.b64 {%0,%1}, %2;" : "=f"(lo), "=f"(hi) : "l"(v));
}
__device__ __forceinline__ u64 fma2(u64 a, u64 b, u64 c) {
    u64 d; asm("fma.rn.f32x2 %0, %1, %2, %3;" : "=l"(d) : "l"(a), "l"(b), "l"(c)); return d;
}
__device__ __forceinline__ u64 add2(u64 a, u64 b) {
    u64 d; asm("add.rn.f32x2 %0, %1, %2;" : "=l"(d) : "l"(a), "l"(b)); return d;
}

// ---------------- activations ----------------
__device__ __forceinline__ float softplusf_(float x) {
    return fmaxf(x, 0.f) + __logf(1.f + __expf(-fabsf(x)));
}
__device__ __forceinline__ float gatef_(float f, float c) {
    float sig = __fdividef(1.f, 1.f + __expf(-f));
    return sig * softplusf_(c);
}

// ---------------- 1: merged prep: detect + folded edge weights + Wcat ----------------
__global__ __launch_bounds__(256) void prep_kernel(
    const unsigned* __restrict__ p2u,
    const float* __restrict__ cheFW, const float* __restrict__ cheFb,
    const float* __restrict__ cheGW, const float* __restrict__ cheGb,
    const float* __restrict__ vdwFW, const float* __restrict__ vdwFb,
    const float* __restrict__ vdwGW, const float* __restrict__ vdwGb)
{
    int bid = blockIdx.x;
    int tid = threadIdx.x;
    if (bid == 0 && tid == 0) g_order = (p2u[0] > 1000000u) ? 1 : 0;

    if (bid < 126) {
        // folded edge weights: We = fW @ gW[128:256, :], be = fb @ gW[...] + gb
        int layer = bid / 42, rem = bid % 42;
        int half = rem / 21, k = rem % 21;
        const float* fW = (half ? vdwFW : cheFW) + layer * 2560;
        const float* fb = (half ? vdwFb : cheFb) + layer * 128;
        const float* gW = (half ? vdwGW : cheGW) + (size_t)layer * 98304;
        const float* gb = (half ? vdwGb : cheGb) + layer * 256;
        float* We = g_We + (layer * 2 + half) * 5120;
        float* be = g_be + (layer * 2 + half) * 256;
        int c = tid;
        if (k < ERBF) {
            float s = 0.f;
            for (int hh = 0; hh < 128; hh++) s = fmaf(fW[k * 128 + hh], gW[(size_t)(128 + hh) * 256 + c], s);
            We[k * 256 + c] = s;
        } else {
            float s = gb[c];
            for (int hh = 0; hh < 128; hh++) s = fmaf(fb[hh], gW[(size_t)(128 + hh) * 256 + c], s);
            be[c] = s;
        }
    } else {
        // Wcat build
        int idx = (bid - 126) * 256 + tid;             // [0, 393216)
        int layer = idx >> 17;
        int within = idx & 131071;
        int k = within >> 10;
        int c = within & 1023;
        int region = c >> 8;                           // 0 S_che, 1 T_che, 2 S_vdw, 3 T_vdw
        int cc = c & 255;
        int h = cc >> 1, p = cc & 1;                   // p=0 filt, p=1 core
        const float* gW = ((region < 2) ? cheGW : vdwGW) + (size_t)layer * 98304;
        int row = ((region & 1) ? 256 : 0) + k;
        g_Wcat[idx] = gW[(size_t)row * 256 + p * 128 + h];
    }
}

// ---------------- 2: node embedding (16 nodes / block) ----------------
__global__ __launch_bounds__(128) void embed_kernel(
    const float* __restrict__ ae, const float* __restrict__ W, const float* __restrict__ b)
{
    __shared__ float sW[13 * 128];
    __shared__ float sa[16 * 13];
    int h = threadIdx.x;
    for (int i = h; i < 13 * 128; i += 128) sW[i] = W[i];
    int n0 = blockIdx.x * 16;
    for (int i = h; i < 16 * 13; i += 128) sa[i] = ae[n0 * 13 + i];
    float bb = b[h];
    __syncthreads();
#pragma unroll
    for (int nn = 0; nn < 16; nn++) {
        float s = bb;
#pragma unroll
        for (int k = 0; k < 13; k++) s = fmaf(sa[nn * 13 + k], sW[k * 128 + h], s);
        g_nodesA[(size_t)(n0 + nn) * 128 + h] = s;
    }
}

// ---------------- 3: ST GEMM  [N,128]x[128,1024], f32x2, double-buffered ----------------
__global__ __launch_bounds__(256, 2) void gemm_kernel(int src, int layer)
{
    const float* __restrict__ A = src ? g_nodesB : g_nodesA;
    const float* __restrict__ Bm = g_Wcat + (size_t)layer * 131072;
    float* __restrict__ C = g_ST;

    __shared__ __align__(16) float As[2][8][128];
    __shared__ __align__(16) float Bs[2][8][128];

    int r0 = blockIdx.x * 128;
    int c0 = blockIdx.y * 128;
    int tid = threadIdx.x;
    int tx = tid & 15, ty = tid >> 4;

    u64 acc[8][4];
#pragma unroll
    for (int i = 0; i < 8; i++)
#pragma unroll
        for (int j = 0; j < 4; j++) acc[i][j] = pk2(0.f, 0.f);

    int arow = tid >> 1;
    int acol = (tid & 1) * 4;
    int brow = tid >> 5;
    int bcol = (tid & 31) * 4;
    int gr = r0 + arow;
    const float* Aptr = A + (size_t)gr * 128 + acol;
    const float* Bptr = Bm + (size_t)brow * 1024 + c0 + bcol;

    float4 av = make_float4(0.f, 0.f, 0.f, 0.f);
    if (gr < NPTS) av = *(const float4*)Aptr;
    float4 bv = *(const float4*)Bptr;
    As[0][acol + 0][arow] = av.x;
    As[0][acol + 1][arow] = av.y;
    As[0][acol + 2][arow] = av.z;
    As[0][acol + 3][arow] = av.w;
    *(float4*)&Bs[0][brow][bcol] = bv;
    __syncthreads();

#pragma unroll 1
    for (int t = 0; t < 16; t++) {
        int cur = t & 1;
        float4 avn = make_float4(0.f, 0.f, 0.f, 0.f), bvn;
        if (t < 15) {
            if (gr < NPTS) avn = *(const float4*)(Aptr + 8 * (t + 1));
            bvn = *(const float4*)(Bptr + (size_t)8 * (t + 1) * 1024);
        }
#pragma unroll
        for (int k = 0; k < 8; k++) {
            ulonglong2 bb0 = *(const ulonglong2*)&Bs[cur][k][tx * 8];
            ulonglong2 bb1 = *(const ulonglong2*)&Bs[cur][k][tx * 8 + 4];
#pragma unroll
            for (int i = 0; i < 8; i++) {
                float a_ = As[cur][k][ty * 8 + i];
                u64 a2 = pk2(a_, a_);
                acc[i][0] = fma2(a2, bb0.x, acc[i][0]);
                acc[i][1] = fma2(a2, bb0.y, acc[i][1]);
                acc[i][2] = fma2(a2, bb1.x, acc[i][2]);
                acc[i][3] = fma2(a2, bb1.y, acc[i][3]);
            }
        }
        if (t < 15) {
            As[cur ^ 1][acol + 0][arow] = avn.x;
            As[cur ^ 1][acol + 1][arow] = avn.y;
            As[cur ^ 1][acol + 2][arow] = avn.z;
            As[cur ^ 1][acol + 3][arow] = avn.w;
            *(float4*)&Bs[cur ^ 1][brow][bcol] = bvn;
        }
        __syncthreads();
    }

#pragma unroll
    for (int i = 0; i < 8; i++) {
        int gr2 = r0 + ty * 8 + i;
        if (gr2 < NPTS) {
            float4 lo, hi;
            upk2(acc[i][0], lo.x, lo.y);
            upk2(acc[i][1], lo.z, lo.w);
            upk2(acc[i][2], hi.x, hi.y);
            upk2(acc[i][3], hi.z, hi.w);
            *(float4*)(C + (size_t)gr2 * 1024 + c0 + tx * 8) = lo;
            *(float4*)(C + (size_t)gr2 * 1024 + c0 + tx * 8 + 4) = hi;
        }
    }
}

// ---------------- 4: fused gated conv: block-level RBF fill, reg accumulators, deep prefetch ----------------
__global__ __launch_bounds__(128) void conv_kernel(
    const float* __restrict__ che_fea, const float* __restrict__ p2f, const float* __restrict__ p3f,
    const int* __restrict__ p2i, const int* __restrict__ p3i,
    const int* __restrict__ vdw_idx, int src, int layer)
{
    const int* che_idx = g_order ? p3i : p2i;
    const float* vdw_fea = g_order ? p2f : p3f;
    const float* __restrict__ nodes = src ? g_nodesB : g_nodesA;
    float* __restrict__ nodes_out = src ? g_nodesA : g_nodesB;

    __shared__ __align__(16) u64 s_r[NBLK * MNBR * ERBF];   // 25.6 KB
    __shared__ int s_idx[NBLK * MNBR];

    int h = threadIdx.x;
    int n0 = blockIdx.x * NBLK;

    float accv[NBLK];
#pragma unroll
    for (int i = 0; i < NBLK; i++) accv[i] = 0.f;

#pragma unroll 1
    for (int half = 0; half < 2; half++) {
        const float* We = g_We + (layer * 2 + half) * 5120;
        const float* be = g_be + (layer * 2 + half) * 256;
        const float* feap = half ? vdw_fea : che_fea;
        const int* idxp = half ? vdw_idx : che_idx;
        float invc = half ? (PI_F / 12.f) : (PI_F / 8.f);
        float cut = half ? 12.f : 8.f;
        int toff = half ? 768 : 256;
        int soff = half ? 512 : 0;

        u64 w[ERBF];
#pragma unroll
        for (int k = 0; k < ERBF; k++) w[k] = pk2(We[k * 256 + h], We[k * 256 + 128 + h]);
        u64 bvec = pk2(be[h], be[128 + h]);

        __syncthreads();   // protect s_r / s_idx reuse across halves
        // one-pass fill: all 8 nodes' RBF (3200 elems) + all idx (160)
        for (int i = h; i < NBLK * MNBR * ERBF; i += 128) {
            int nn = i / (MNBR * ERBF);
            int r = i - nn * (MNBR * ERBF);
            int m = r / ERBF;
            int k = r - m * ERBF;
            float d = feap[(n0 + nn) * MNBR + m];
            float v = 0.f;
            if (d < cut) {
                float env = 0.5f * (__cosf(d * invc) + 1.f) * __fdividef(1.f, d);
                v = __sinf(d * ((float)(k + 1) * invc)) * env;
            }
            s_r[i] = pk2(v, v);
        }
        for (int i = h; i < NBLK * MNBR; i += 128) s_idx[i] = idxp[n0 * MNBR + i];
        __syncthreads();

#pragma unroll 1
        for (int nn = 0; nn < NBLK; nn++) {
            int n = n0 + nn;
            u64 sv = *(const u64*)(g_ST + (size_t)n * 1024 + soff + 2 * h);
            u64 base = add2(bvec, sv);
            const int* idxl = s_idx + nn * MNBR;
            const u64* rr_base = s_r + nn * (MNBR * ERBF);

            // 3-deep gather prefetch
            u64 t0 = *(const u64*)(g_ST + (size_t)idxl[0] * 1024 + toff + 2 * h);
            u64 t1 = *(const u64*)(g_ST + (size_t)idxl[1] * 1024 + toff + 2 * h);
            u64 t2 = *(const u64*)(g_ST + (size_t)idxl[2] * 1024 + toff + 2 * h);

            float a = 0.f;
#pragma unroll 1
            for (int m = 0; m < MNBR; m++) {
                u64 tcur = t0;
                t0 = t1; t1 = t2;
                int mp = (m + 3 < MNBR) ? (m + 3) : (MNBR - 1);
                t2 = *(const u64*)(g_ST + (size_t)idxl[mp] * 1024 + toff + 2 * h);

                u64 e0 = base, e1 = pk2(0.f, 0.f);
#pragma unroll
                for (int k = 0; k < ERBF; k += 4) {
                    ulonglong2 ra = *(const ulonglong2*)&rr_base[m * ERBF + k];
                    ulonglong2 rb = *(const ulonglong2*)&rr_base[m * ERBF + k + 2];
                    e0 = fma2(ra.x, w[k],     e0);
                    e1 = fma2(ra.y, w[k + 1], e1);
                    e0 = fma2(rb.x, w[k + 2], e0);
                    e1 = fma2(rb.y, w[k + 3], e1);
                }
                u64 g = add2(add2(e0, e1), tcur);
                float gf, gc; upk2(g, gf, gc);
                a += gatef_(gf, gc);
            }
            accv[nn] += a;
        }
    }
#pragma unroll
    for (int nn = 0; nn < NBLK; nn++) {
        int n = n0 + nn;
        float r = nodes[(size_t)n * 128 + h] + accv[nn];
        nodes_out[(size_t)n * 128 + h] = softplusf_(r);
    }
}

// ---------------- 5: pooling + MLP head ----------------
__global__ __launch_bounds__(128) void pool_kernel(
    const int* __restrict__ num_atoms,
    const float* __restrict__ fc1W, const float* __restrict__ fc1b,
    const float* __restrict__ outW, const float* __restrict__ outb,
    float* __restrict__ out, int src)
{
    const float* __restrict__ nodes = src ? g_nodesB : g_nodesA;
    __shared__ float sA[128];
    __shared__ float sB[128];
    __shared__ int sred[128];
    int b = blockIdx.x, h = threadIdx.x;

    int v = 0;
    for (int i = h; i < b; i += 128) v += num_atoms[i];
    sred[h] = v;
    __syncthreads();
    for (int off = 64; off > 0; off >>= 1) {
        if (h < off) sred[h] += sred[h + off];
        __syncthreads();
    }
    int start = sred[0];
    int cnt = num_atoms[b];

    float s = 0.f;
    for (int a = 0; a < cnt; a++) s += nodes[(size_t)(start + a) * 128 + h];
    sA[h] = softplusf_(s / (float)cnt);
    __syncthreads();
    float t = fc1b[h];
    for (int k = 0; k < 128; k++) t = fmaf(sA[k], fc1W[k * 128 + h], t);
    sB[h] = softplusf_(t) * outW[h];
    __syncthreads();
    for (int off = 64; off > 0; off >>= 1) {
        if (h < off) sB[h] += sB[h + off];
        __syncthreads();
    }
    if (h == 0) out[b] = sB[0] + outb[0];
}

// ---------------- launch ----------------
extern "C" void kernel_launch(void* const* d_in, const int* in_sizes, int n_in,
                              void* d_out, int out_size)
{
    const float* ae      = (const float*)d_in[0];
    const float* che_fea = (const float*)d_in[1];
    const void*  p2      = d_in[2];
    const void*  p3      = d_in[3];
    const int*   vdw_idx = (const int*)d_in[4];
    const int*   natoms  = (const int*)d_in[5];
    const float* embW    = (const float*)d_in[6];
    const float* embB    = (const float*)d_in[7];
    const float* cheFW   = (const float*)d_in[8];
    const float* cheFb   = (const float*)d_in[9];
    const float* cheGW   = (const float*)d_in[10];
    const float* cheGb   = (const float*)d_in[11];
    const float* vdwFW   = (const float*)d_in[12];
    const float* vdwFb   = (const float*)d_in[13];
    const float* vdwGW   = (const float*)d_in[14];
    const float* vdwGb   = (const float*)d_in[15];
    const float* fc1W    = (const float*)d_in[16];
    const float* fc1b    = (const float*)d_in[17];
    const float* outW    = (const float*)d_in[18];
    const float* outb    = (const float*)d_in[19];

    prep_kernel<<<126 + 1536, 256>>>((const unsigned*)p2, cheFW, cheFb, cheGW, cheGb,
                                     vdwFW, vdwFb, vdwGW, vdwGb);
    embed_kernel<<<NPTS / 16, 128>>>(ae, embW, embB);

    int src = 0;
    for (int i = 0; i < 3; i++) {
        gemm_kernel<<<dim3((NPTS + 127) / 128, 8), 256>>>(src, i);
        conv_kernel<<<NPTS / NBLK, 128>>>(che_fea, (const float*)p2, (const float*)p3,
                                          (const int*)p2, (const int*)p3, vdw_idx, src, i);
        src ^= 1;
    }
    pool_kernel<<<BCRY, 128>>>(natoms, fc1W, fc1b, outW, outb, (float*)d_out, src);
}

// round 4
// speedup vs baseline: 1.5777x; 1.2997x over previous
#include <cuda_runtime.h>
#include <cstdint>

// ---------------- problem constants ----------------
#define NPTS 20000
#define MNBR 20
#define ERBF 20
#define HDIM 128
#define BCRY 200
#define NBLK 8
#define PI_F 3.14159265358979f
#define KNOT 4096
#define DMAX_CHE 8.81f
#define DMAX_VDW 13.21f

typedef unsigned long long u64;

// ---------------- device scratch ----------------
__device__ int   g_order;
__device__ float g_nodesA[NPTS * HDIM];
__device__ float g_nodesB[NPTS * HDIM];
__device__ float g_ST[(size_t)NPTS * 1024];        // [S_che|T_che|S_vdw|T_vdw] interleaved (filt,core)
__device__ float g_Wcat[3 * 131072];
__device__ float g_We[3 * 2 * ERBF * 256];
__device__ float g_be[3 * 2 * 256];
__device__ float g_tab[(size_t)3 * 2 * KNOT * 256]; // edge tables: value includes be, env/d, cutoff mask

// ---------------- f32x2 packed math ----------------
__device__ __forceinline__ u64 pk2(float lo, float hi) {
    u64 r; asm("mov.b64 %0, {%1,%2};" : "=l"(r) : "f"(lo), "f"(hi)); return r;
}
__device__ __forceinline__ void upk2(u64 v, float& lo, float& hi) {
    asm("mov.b64 {%0,%1}, %2;" : "=f"(lo), "=f"(hi) : "l"(v));
}
__device__ __forceinline__ u64 fma2(u64 a, u64 b, u64 c) {
    u64 d; asm("fma.rn.f32x2 %0, %1, %2, %3;" : "=l"(d) : "l"(a), "l"(b), "l"(c)); return d;
}
__device__ __forceinline__ u64 add2(u64 a, u64 b) {
    u64 d; asm("add.rn.f32x2 %0, %1, %2;" : "=l"(d) : "l"(a), "l"(b)); return d;
}
__device__ __forceinline__ u64 mul2(u64 a, u64 b) {
    u64 d; asm("mul.rn.f32x2 %0, %1, %2;" : "=l"(d) : "l"(a), "l"(b)); return d;
}

// ---------------- activations ----------------
__device__ __forceinline__ float softplusf_(float x) {
    return fmaxf(x, 0.f) + __logf(1.f + __expf(-fabsf(x)));
}
__device__ __forceinline__ float gatef_(float f, float c) {
    float sig = __fdividef(1.f, 1.f + __expf(-f));
    return sig * softplusf_(c);
}

// ---------------- 1: merged prep: detect + folded edge weights + Wcat ----------------
__global__ __launch_bounds__(256) void prep_kernel(
    const unsigned* __restrict__ p2u,
    const float* __restrict__ cheFW, const float* __restrict__ cheFb,
    const float* __restrict__ cheGW, const float* __restrict__ cheGb,
    const float* __restrict__ vdwFW, const float* __restrict__ vdwFb,
    const float* __restrict__ vdwGW, const float* __restrict__ vdwGb)
{
    int bid = blockIdx.x;
    int tid = threadIdx.x;
    if (bid == 0 && tid == 0) g_order = (p2u[0] > 1000000u) ? 1 : 0;

    if (bid < 126) {
        int layer = bid / 42, rem = bid % 42;
        int half = rem / 21, k = rem % 21;
        const float* fW = (half ? vdwFW : cheFW) + layer * 2560;
        const float* fb = (half ? vdwFb : cheFb) + layer * 128;
        const float* gW = (half ? vdwGW : cheGW) + (size_t)layer * 98304;
        const float* gb = (half ? vdwGb : cheGb) + layer * 256;
        float* We = g_We + (layer * 2 + half) * 5120;
        float* be = g_be + (layer * 2 + half) * 256;
        int c = tid;
        if (k < ERBF) {
            float s = 0.f;
            for (int hh = 0; hh < 128; hh++) s = fmaf(fW[k * 128 + hh], gW[(size_t)(128 + hh) * 256 + c], s);
            We[k * 256 + c] = s;
        } else {
            float s = gb[c];
            for (int hh = 0; hh < 128; hh++) s = fmaf(fb[hh], gW[(size_t)(128 + hh) * 256 + c], s);
            be[c] = s;
        }
    } else {
        int idx = (bid - 126) * 256 + tid;             // [0, 393216)
        int layer = idx >> 17;
        int within = idx & 131071;
        int k = within >> 10;
        int c = within & 1023;
        int region = c >> 8;                           // 0 S_che, 1 T_che, 2 S_vdw, 3 T_vdw
        int cc = c & 255;
        int h = cc >> 1, p = cc & 1;                   // p=0 filt, p=1 core
        const float* gW = ((region < 2) ? cheGW : vdwGW) + (size_t)layer * 98304;
        int row = ((region & 1) ? 256 : 0) + k;
        g_Wcat[idx] = gW[(size_t)row * 256 + p * 128 + h];
    }
}

// ---------------- 2: edge lookup tables via Chebyshev recurrence ----------------
__global__ __launch_bounds__(256) void table_kernel()
{
    int j = blockIdx.x;           // knot
    int lh = blockIdx.y;          // layer*2 + half
    int half = lh & 1;
    int cc = threadIdx.x;         // row position (filt,core interleaved)
    int h = cc >> 1, p = cc & 1;
    int col = p * 128 + h;

    const float* We = g_We + lh * 5120;
    const float* be = g_be + lh * 256;
    float cut  = half ? 12.f : 8.f;
    float dmax = half ? DMAX_VDW : DMAX_CHE;
    float d = (float)j * (dmax / (float)(KNOT - 3));

    float val = be[col];
    if (d < cut) {
        float x = d * (PI_F / cut);
        float s1, c1;
        s1 = sinf(x); c1 = cosf(x);                    // precise, small args
        float env = 0.5f * (c1 + 1.f);
        float invd = (d > 1e-6f) ? __fdividef(1.f, d) : 0.f;
        float coef = env * invd;
        float c2 = 2.f * c1;
        float sk = s1, skm = 0.f;                      // sk = sin((k+1)x)
#pragma unroll
        for (int k = 0; k < ERBF; k++) {
            val = fmaf(sk * coef, We[k * 256 + col], val);
            float sn = fmaf(c2, sk, -skm);
            skm = sk; sk = sn;
        }
    }
    g_tab[((size_t)lh * KNOT + j) * 256 + cc] = val;
}

// ---------------- 3: node embedding ----------------
__global__ __launch_bounds__(128) void embed_kernel(
    const float* __restrict__ ae, const float* __restrict__ W, const float* __restrict__ b)
{
    __shared__ float sW[13 * 128];
    __shared__ float sa[16 * 13];
    int h = threadIdx.x;
    for (int i = h; i < 13 * 128; i += 128) sW[i] = W[i];
    int n0 = blockIdx.x * 16;
    for (int i = h; i < 16 * 13; i += 128) sa[i] = ae[n0 * 13 + i];
    float bb = b[h];
    __syncthreads();
#pragma unroll
    for (int nn = 0; nn < 16; nn++) {
        float s = bb;
#pragma unroll
        for (int k = 0; k < 13; k++) s = fmaf(sa[nn * 13 + k], sW[k * 128 + h], s);
        g_nodesA[(size_t)(n0 + nn) * 128 + h] = s;
    }
}

// ---------------- 4: ST GEMM  [N,128]x[128,1024], f32x2, double-buffered ----------------
__global__ __launch_bounds__(256, 2) void gemm_kernel(int src, int layer)
{
    const float* __restrict__ A = src ? g_nodesB : g_nodesA;
    const float* __restrict__ Bm = g_Wcat + (size_t)layer * 131072;
    float* __restrict__ C = g_ST;

    __shared__ __align__(16) float As[2][8][128];
    __shared__ __align__(16) float Bs[2][8][128];

    int r0 = blockIdx.x * 128;
    int c0 = blockIdx.y * 128;
    int tid = threadIdx.x;
    int tx = tid & 15, ty = tid >> 4;

    u64 acc[8][4];
#pragma unroll
    for (int i = 0; i < 8; i++)
#pragma unroll
        for (int j = 0; j < 4; j++) acc[i][j] = pk2(0.f, 0.f);

    int arow = tid >> 1;
    int acol = (tid & 1) * 4;
    int brow = tid >> 5;
    int bcol = (tid & 31) * 4;
    int gr = r0 + arow;
    const float* Aptr = A + (size_t)gr * 128 + acol;
    const float* Bptr = Bm + (size_t)brow * 1024 + c0 + bcol;

    float4 av = make_float4(0.f, 0.f, 0.f, 0.f);
    if (gr < NPTS) av = *(const float4*)Aptr;
    float4 bv = *(const float4*)Bptr;
    As[0][acol + 0][arow] = av.x;
    As[0][acol + 1][arow] = av.y;
    As[0][acol + 2][arow] = av.z;
    As[0][acol + 3][arow] = av.w;
    *(float4*)&Bs[0][brow][bcol] = bv;
    __syncthreads();

#pragma unroll 1
    for (int t = 0; t < 16; t++) {
        int cur = t & 1;
        float4 avn = make_float4(0.f, 0.f, 0.f, 0.f), bvn;
        if (t < 15) {
            if (gr < NPTS) avn = *(const float4*)(Aptr + 8 * (t + 1));
            bvn = *(const float4*)(Bptr + (size_t)8 * (t + 1) * 1024);
        }
#pragma unroll
        for (int k = 0; k < 8; k++) {
            ulonglong2 bb0 = *(const ulonglong2*)&Bs[cur][k][tx * 8];
            ulonglong2 bb1 = *(const ulonglong2*)&Bs[cur][k][tx * 8 + 4];
#pragma unroll
            for (int i = 0; i < 8; i++) {
                float a_ = As[cur][k][ty * 8 + i];
                u64 a2 = pk2(a_, a_);
                acc[i][0] = fma2(a2, bb0.x, acc[i][0]);
                acc[i][1] = fma2(a2, bb0.y, acc[i][1]);
                acc[i][2] = fma2(a2, bb1.x, acc[i][2]);
                acc[i][3] = fma2(a2, bb1.y, acc[i][3]);
            }
        }
        if (t < 15) {
            As[cur ^ 1][acol + 0][arow] = avn.x;
            As[cur ^ 1][acol + 1][arow] = avn.y;
            As[cur ^ 1][acol + 2][arow] = avn.z;
            As[cur ^ 1][acol + 3][arow] = avn.w;
            *(float4*)&Bs[cur ^ 1][brow][bcol] = bvn;
        }
        __syncthreads();
    }

#pragma unroll
    for (int i = 0; i < 8; i++) {
        int gr2 = r0 + ty * 8 + i;
        if (gr2 < NPTS) {
            float4 lo, hi;
            upk2(acc[i][0], lo.x, lo.y);
            upk2(acc[i][1], lo.z, lo.w);
            upk2(acc[i][2], hi.x, hi.y);
            upk2(acc[i][3], hi.z, hi.w);
            *(float4*)(C + (size_t)gr2 * 1024 + c0 + tx * 8) = lo;
            *(float4*)(C + (size_t)gr2 * 1024 + c0 + tx * 8 + 4) = hi;
        }
    }
}

// ---------------- 5: fused gated conv with table-lookup edges ----------------
__global__ __launch_bounds__(128) void conv_kernel(
    const float* __restrict__ che_fea, const float* __restrict__ p2f, const float* __restrict__ p3f,
    const int* __restrict__ p2i, const int* __restrict__ p3i,
    const int* __restrict__ vdw_idx, int src, int layer)
{
    const int* che_idx = g_order ? p3i : p2i;
    const float* vdw_fea = g_order ? p2f : p3f;
    const float* __restrict__ nodes = src ? g_nodesB : g_nodesA;
    float* __restrict__ nodes_out = src ? g_nodesA : g_nodesB;

    __shared__ int  s_idx[NBLK * MNBR];
    __shared__ int  s_joff[NBLK * MNBR];
    __shared__ u64  s_fr[NBLK * MNBR];
    __shared__ u64  s_frm[NBLK * MNBR];

    int h = threadIdx.x;
    int h2 = 2 * h;
    int n0 = blockIdx.x * NBLK;

    float accv[NBLK];
#pragma unroll
    for (int i = 0; i < NBLK; i++) accv[i] = 0.f;

#pragma unroll 1
    for (int half = 0; half < 2; half++) {
        const float* tab = g_tab + ((size_t)(layer * 2 + half) * KNOT) * 256;
        const float* feap = half ? vdw_fea : che_fea;
        const int* idxp = half ? vdw_idx : che_idx;
        float scale = half ? ((float)(KNOT - 3) / DMAX_VDW) : ((float)(KNOT - 3) / DMAX_CHE);
        int toff = half ? 768 : 256;
        int soff = half ? 512 : 0;

        __syncthreads();     // protect reuse of shared arrays across halves
        for (int i = h; i < NBLK * MNBR; i += 128) {
            float d = feap[n0 * MNBR + i];
            float u = fminf(d * scale, (float)(KNOT - 3));
            float jf = floorf(u);
            float fr = u - jf;
            s_joff[i] = (int)jf * 256;
            s_fr[i]  = pk2(fr, fr);
            s_frm[i] = pk2(1.f - fr, 1.f - fr);
            s_idx[i] = idxp[n0 * MNBR + i];
        }
        __syncthreads();

#pragma unroll 1
        for (int nn = 0; nn < NBLK; nn++) {
            int n = n0 + nn;
            u64 sv = *(const u64*)(g_ST + (size_t)n * 1024 + soff + h2);
            int i0 = nn * MNBR;

            // 1-ahead pipeline for gather + table rows
            int jo = s_joff[i0];
            u64 tg = *(const u64*)(g_ST + (size_t)s_idx[i0] * 1024 + toff + h2);
            u64 t0 = *(const u64*)(tab + jo + h2);
            u64 t1 = *(const u64*)(tab + jo + 256 + h2);

            float a = 0.f;
#pragma unroll 1
            for (int m = 0; m < MNBR; m++) {
                u64 tgc = tg, t0c = t0, t1c = t1;
                int mn = (m + 1 < MNBR) ? (m + 1) : (MNBR - 1);
                int jon = s_joff[i0 + mn];
                tg = *(const u64*)(g_ST + (size_t)s_idx[i0 + mn] * 1024 + toff + h2);
                t0 = *(const u64*)(tab + jon + h2);
                t1 = *(const u64*)(tab + jon + 256 + h2);

                u64 e = fma2(s_fr[i0 + m], t1c, mul2(s_frm[i0 + m], t0c));
                u64 g = add2(add2(sv, tgc), e);
                float gf, gc; upk2(g, gf, gc);
                a += gatef_(gf, gc);
            }
            accv[nn] += a;
        }
    }
#pragma unroll
    for (int nn = 0; nn < NBLK; nn++) {
        int n = n0 + nn;
        float r = nodes[(size_t)n * 128 + h] + accv[nn];
        nodes_out[(size_t)n * 128 + h] = softplusf_(r);
    }
}

// ---------------- 6: pooling + MLP head ----------------
__global__ __launch_bounds__(128) void pool_kernel(
    const int* __restrict__ num_atoms,
    const float* __restrict__ fc1W, const float* __restrict__ fc1b,
    const float* __restrict__ outW, const float* __restrict__ outb,
    float* __restrict__ out, int src)
{
    const float* __restrict__ nodes = src ? g_nodesB : g_nodesA;
    __shared__ float sA[128];
    __shared__ float sB[128];
    __shared__ int sred[128];
    int b = blockIdx.x, h = threadIdx.x;

    int v = 0;
    for (int i = h; i < b; i += 128) v += num_atoms[i];
    sred[h] = v;
    __syncthreads();
    for (int off = 64; off > 0; off >>= 1) {
        if (h < off) sred[h] += sred[h + off];
        __syncthreads();
    }
    int start = sred[0];
    int cnt = num_atoms[b];

    float s = 0.f;
    for (int a = 0; a < cnt; a++) s += nodes[(size_t)(start + a) * 128 + h];
    sA[h] = softplusf_(s / (float)cnt);
    __syncthreads();
    float t = fc1b[h];
    for (int k = 0; k < 128; k++) t = fmaf(sA[k], fc1W[k * 128 + h], t);
    sB[h] = softplusf_(t) * outW[h];
    __syncthreads();
    for (int off = 64; off > 0; off >>= 1) {
        if (h < off) sB[h] += sB[h + off];
        __syncthreads();
    }
    if (h == 0) out[b] = sB[0] + outb[0];
}

// ---------------- launch ----------------
extern "C" void kernel_launch(void* const* d_in, const int* in_sizes, int n_in,
                              void* d_out, int out_size)
{
    const float* ae      = (const float*)d_in[0];
    const float* che_fea = (const float*)d_in[1];
    const void*  p2      = d_in[2];
    const void*  p3      = d_in[3];
    const int*   vdw_idx = (const int*)d_in[4];
    const int*   natoms  = (const int*)d_in[5];
    const float* embW    = (const float*)d_in[6];
    const float* embB    = (const float*)d_in[7];
    const float* cheFW   = (const float*)d_in[8];
    const float* cheFb   = (const float*)d_in[9];
    const float* cheGW   = (const float*)d_in[10];
    const float* cheGb   = (const float*)d_in[11];
    const float* vdwFW   = (const float*)d_in[12];
    const float* vdwFb   = (const float*)d_in[13];
    const float* vdwGW   = (const float*)d_in[14];
    const float* vdwGb   = (const float*)d_in[15];
    const float* fc1W    = (const float*)d_in[16];
    const float* fc1b    = (const float*)d_in[17];
    const float* outW    = (const float*)d_in[18];
    const float* outb    = (const float*)d_in[19];

    prep_kernel<<<126 + 1536, 256>>>((const unsigned*)p2, cheFW, cheFb, cheGW, cheGb,
                                     vdwFW, vdwFb, vdwGW, vdwGb);
    table_kernel<<<dim3(KNOT, 6), 256>>>();
    embed_kernel<<<NPTS / 16, 128>>>(ae, embW, embB);

    int src = 0;
    for (int i = 0; i < 3; i++) {
        gemm_kernel<<<dim3((NPTS + 127) / 128, 8), 256>>>(src, i);
        conv_kernel<<<NPTS / NBLK, 128>>>(che_fea, (const float*)p2, (const float*)p3,
                                          (const int*)p2, (const int*)p3, vdw_idx, src, i);
        src ^= 1;
    }
    pool_kernel<<<BCRY, 128>>>(natoms, fc1W, fc1b, outW, outb, (float*)d_out, src);
}